// round 4
// baseline (speedup 1.0000x reference)
#include <cuda_runtime.h>
#include <math.h>

#define NN 8192
#define DD 64
#define CC 100
#define TT 30
#define HC 50          // classes per grid.y (2 classes per block)
#define NPAIR 465      // TT*(TT+1)/2 inclusive-diagonal pairs

// ---- device-global scratch ----
__device__ float g_lp[CC * NN];        // lp[c][n]

typedef unsigned long long u64;

// ---- packed f32x2 helpers (sm_103a FFMA2) ----
__device__ __forceinline__ float2 upk2(u64 v) {
    float2 f; asm("mov.b64 {%0, %1}, %2;" : "=f"(f.x), "=f"(f.y) : "l"(v)); return f;
}
__device__ __forceinline__ u64 fma2(u64 a, u64 b, u64 c) {
    u64 d; asm("fma.rn.f32x2 %0, %1, %2, %3;" : "=l"(d) : "l"(a), "l"(b), "l"(c)); return d;
}
__device__ __forceinline__ u64 add2(u64 a, u64 b) {
    u64 d; asm("add.rn.f32x2 %0, %1, %2;" : "=l"(d) : "l"(a), "l"(b)); return d;
}

// dynamic smem layout (floats):
//  sz0 : 2*TT*64  = 3840   [0)
//  sG  : 2*TT*32  = 1920   [3840)
//  sprm: 2*96     = 192    [5760)   (al@+0, be@+32, n0@+64 per class)
//  sp  : 2*TT*128 = 7680   [5952)
#define OFF_Z0  0
#define OFF_G   3840
#define OFF_PRM 5760
#define OFF_P   5952
#define SMEM_FLOATS 13632
#define SMEM_BYTES  (SMEM_FLOATS * 4)

// ---- flow: block = (128 samples) x (2 classes); thread = 2 interleaved chains ----
__global__ void __launch_bounds__(128, 4) flow_kernel(const float* __restrict__ x,
                                                      const float* __restrict__ z0g,
                                                      const float* __restrict__ apg,
                                                      const float* __restrict__ bpg) {
    extern __shared__ __align__(16) float sm[];
    float* sz0 = sm + OFF_Z0;
    float* sG  = sm + OFF_G;
    float* sprm = sm + OFF_PRM;
    float* sp  = sm + OFF_P;

    const int tid = threadIdx.x;
    const int c0 = blockIdx.y;
    const int c1 = blockIdx.y + HC;
    const int n = blockIdx.x * 128 + tid;

    // ---- stage z0 for both classes (coalesced float4) ----
    {
        const float4* gz0 = (const float4*)(z0g + (size_t)c0 * TT * DD);
        const float4* gz1 = (const float4*)(z0g + (size_t)c1 * TT * DD);
        float4* s4 = (float4*)sz0;
        #pragma unroll
        for (int i = tid; i < 480; i += 128) s4[i] = gz0[i];
        #pragma unroll
        for (int i = tid; i < 480; i += 128) s4[480 + i] = gz1[i];
    }
    // ---- own x row -> packed regs (L2-resident) ----
    u64 xv[32];
    {
        const float4* xp = (const float4*)(x + (size_t)n * DD);
        #pragma unroll
        for (int j = 0; j < 16; ++j) {
            float4 v = __ldg(xp + j);
            asm("mov.b64 %0, {%1, %2};" : "=l"(xv[2 * j])     : "f"(v.x), "f"(v.y));
            asm("mov.b64 %0, {%1, %2};" : "=l"(xv[2 * j + 1]) : "f"(v.z), "f"(v.w));
        }
    }
    float q0;
    {
        u64 a0 = 0ull, a1 = 0ull, a2 = 0ull, a3 = 0ull;
        #pragma unroll
        for (int j = 0; j < 32; j += 4) {
            a0 = fma2(xv[j],     xv[j],     a0);
            a1 = fma2(xv[j + 1], xv[j + 1], a1);
            a2 = fma2(xv[j + 2], xv[j + 2], a2);
            a3 = fma2(xv[j + 3], xv[j + 3], a3);
        }
        float2 f = upk2(add2(add2(a0, a1), add2(a2, a3)));
        q0 = f.x + f.y;
    }
    // softplus params (threads 0..59), direct from global
    if (tid < 60) {
        int cls = tid / TT, t = tid % TT;
        int c = cls ? c1 : c0;
        float a  = log1pf(__expf(apg[c * TT + t]));
        float be = log1pf(__expf(bpg[c * TT + t])) - a;
        sprm[cls * 96 + t]      = a;
        sprm[cls * 96 + 32 + t] = be;
    }
    __syncthreads();

    // ---- Gram (incl. diagonal -> n0) for both classes, inline ----
    for (int k = tid; k < 2 * NPAIR; k += 128) {
        int cls = (k >= NPAIR);
        int kk = k - cls * NPAIR;
        int t = (int)((__fsqrt_rn(8.f * kk + 1.f) - 1.f) * 0.5f);
        while ((t + 1) * (t + 2) / 2 <= kk) ++t;
        while (t * (t + 1) / 2 > kk) --t;
        int i = kk - t * (t + 1) / 2;
        const ulonglong2* za = (const ulonglong2*)(sz0 + cls * 1920 + t * DD);
        const ulonglong2* zb = (const ulonglong2*)(sz0 + cls * 1920 + i * DD);
        u64 a0 = 0ull, a1 = 0ull, a2 = 0ull, a3 = 0ull;
        #pragma unroll
        for (int j = 0; j < 16; j += 2) {
            ulonglong2 va = za[j], vb = zb[j];
            ulonglong2 va2 = za[j + 1], vb2 = zb[j + 1];
            a0 = fma2(va.x,  vb.x,  a0);
            a1 = fma2(va.y,  vb.y,  a1);
            a2 = fma2(va2.x, vb2.x, a2);
            a3 = fma2(va2.y, vb2.y, a3);
        }
        float2 f = upk2(add2(add2(a0, a1), add2(a2, a3)));
        float dot = f.x + f.y;
        if (i == t) sprm[cls * 96 + 64 + t] = dot;
        else        sG[cls * 960 + t * 32 + i] = dot;
    }

    // ---- P phase (rolled): p[cls][t] = x . z0[cls][t] ----
    #pragma unroll 1
    for (int t = 0; t < TT; ++t) {
        const ulonglong2* zp0 = (const ulonglong2*)(sz0 + t * DD);
        const ulonglong2* zp1 = (const ulonglong2*)(sz0 + 1920 + t * DD);
        u64 a0 = 0ull, a1 = 0ull, a2 = 0ull, a3 = 0ull;
        u64 b0 = 0ull, b1 = 0ull, b2 = 0ull, b3 = 0ull;
        #pragma unroll
        for (int j = 0; j < 16; j += 2) {
            ulonglong2 v0 = zp0[j], v1 = zp0[j + 1];
            ulonglong2 u0 = zp1[j], u1 = zp1[j + 1];
            a0 = fma2(xv[2 * j],     v0.x, a0);
            a1 = fma2(xv[2 * j + 1], v0.y, a1);
            a2 = fma2(xv[2 * j + 2], v1.x, a2);
            a3 = fma2(xv[2 * j + 3], v1.y, a3);
            b0 = fma2(xv[2 * j],     u0.x, b0);
            b1 = fma2(xv[2 * j + 1], u0.y, b1);
            b2 = fma2(xv[2 * j + 2], u1.x, b2);
            b3 = fma2(xv[2 * j + 3], u1.y, b3);
        }
        float2 fa = upk2(add2(add2(a0, a1), add2(a2, a3)));
        float2 fb = upk2(add2(add2(b0, b1), add2(b2, b3)));
        sp[t * 128 + tid]        = fa.x + fa.y;
        sp[3840 + t * 128 + tid] = fb.x + fb.y;
    }
    __syncthreads();

    // ---- scalar chains, 2 classes interleaved ----
    float w0[TT], w1[TT];
    float ldA = 0.f, gA = 1.f, qA = q0;
    float ldB = 0.f, gB = 1.f, qB = q0;
    const float* al0 = sprm;          const float* be0 = sprm + 32;  const float* n00 = sprm + 64;
    const float* al1 = sprm + 96;     const float* be1 = sprm + 128; const float* n01 = sprm + 160;

    #pragma unroll
    for (int t = 0; t < TT; ++t) {
        float accA0 = sp[t * 128 + tid],        accA1 = 0.f;
        float accB0 = sp[3840 + t * 128 + tid], accB1 = 0.f;
        const float* GrA = sG + t * 32;
        const float* GrB = sG + 960 + t * 32;
        int i = 0;
        #pragma unroll
        for (; i + 4 <= t; i += 4) {
            float4 gx = *(const float4*)(GrA + i);
            float4 gy = *(const float4*)(GrB + i);
            accA0 = fmaf(w0[i],     gx.x, accA0);
            accA1 = fmaf(w0[i + 1], gx.y, accA1);
            accA0 = fmaf(w0[i + 2], gx.z, accA0);
            accA1 = fmaf(w0[i + 3], gx.w, accA1);
            accB0 = fmaf(w1[i],     gy.x, accB0);
            accB1 = fmaf(w1[i + 1], gy.y, accB1);
            accB0 = fmaf(w1[i + 2], gy.z, accB0);
            accB1 = fmaf(w1[i + 3], gy.w, accB1);
        }
        #pragma unroll
        for (; i < t; ++i) {
            accA0 = fmaf(w0[i], GrA[i], accA0);
            accB0 = fmaf(w1[i], GrB[i], accB0);
        }
        float sA = gA * (accA0 + accA1);
        float sB = gB * (accB0 + accB1);

        float alA = al0[t], beA = be0[t], nnA = n00[t];
        float alB = al1[t], beB = be1[t], nnB = n01[t];

        float r2A = fmaxf(fmaf(-2.f, sA, qA) + nnA, 1e-20f);
        float r2B = fmaxf(fmaf(-2.f, sB, qB) + nnB, 1e-20f);
        float rinA = rsqrtf(r2A), rinB = rsqrtf(r2B);
        float rA = r2A * rinA,    rB = r2B * rinB;
        float hA = __fdividef(1.f, alA + rA);
        float hB = __fdividef(1.f, alB + rB);
        float bhA = beA * hA,     bhB = beB * hB;
        float opA = 1.f + bhA,    opB = 1.f + bhB;
        float t2A = opA - bhA * hA * rA;
        float t2B = opB - bhB * hB * rB;
        ldA += 63.f * __logf(opA) + __logf(t2A);
        ldB += 63.f * __logf(opB) + __logf(t2B);
        qA = fmaf(bhA * bhA, r2A, fmaf(2.f * bhA, qA - sA, qA));
        qB = fmaf(bhB * bhB, r2B, fmaf(2.f * bhB, qB - sB, qB));
        float g2A = gA * opA, g2B = gB * opB;
        w0[t] = -__fdividef(bhA, g2A);
        w1[t] = -__fdividef(bhB, g2B);
        gA = g2A; gB = g2B;
    }

    g_lp[(size_t)c0 * NN + n] = ldA - 0.5f * qA - 58.8120661251f;
    g_lp[(size_t)c1 * NN + n] = ldB - 0.5f * qB - 58.8120661251f;
}

// ---- epilogue: warp = sample ----
__global__ void __launch_bounds__(256) out_kernel(const float* __restrict__ x,
                                                  const int* __restrict__ labels,
                                                  const float* __restrict__ freq,
                                                  const float* __restrict__ W,
                                                  const float* __restrict__ b,
                                                  float* __restrict__ out) {
    __shared__ __align__(16) float sWt[CC * 68];
    __shared__ __align__(16) float sxr[8 * 68];
    __shared__ float sb[CC], slf[CC];
    const int tid = threadIdx.x;
    for (int i = tid; i < DD * CC; i += 256) {
        int d = i / CC, cc = i % CC;
        sWt[cc * 68 + d] = W[i];
    }
    for (int i = tid; i < CC; i += 256) { sb[i] = b[i]; slf[i] = __logf(freq[i]); }

    const int wid = tid >> 5, lane = tid & 31;
    const int n = blockIdx.x * 8 + wid;
    {
        const float2* xp = (const float2*)(x + (size_t)n * DD);
        ((float2*)(sxr + wid * 68))[lane] = xp[lane];
    }
    __syncthreads();

    u64 xv[32];
    {
        const ulonglong2* xr = (const ulonglong2*)(sxr + wid * 68);
        #pragma unroll
        for (int j = 0; j < 16; ++j) {
            ulonglong2 v = xr[j];
            xv[2 * j] = v.x; xv[2 * j + 1] = v.y;
        }
    }

    float lg[4], lq[4];
    float mlg = -1e30f, mlp = -1e30f;
    #pragma unroll
    for (int k = 0; k < 4; ++k) {
        int cc = lane + 32 * k;
        if (cc < CC) {
            const ulonglong2* wr = (const ulonglong2*)(sWt + cc * 68);
            u64 a0 = 0ull, a1 = 0ull;
            #pragma unroll
            for (int j = 0; j < 16; ++j) {
                ulonglong2 v = wr[j];
                a0 = fma2(xv[2 * j],     v.x, a0);
                a1 = fma2(xv[2 * j + 1], v.y, a1);
            }
            float2 f = upk2(add2(a0, a1));
            lg[k] = f.x + f.y + sb[cc];
            lq[k] = g_lp[(size_t)cc * NN + n] + slf[cc];
        } else {
            lg[k] = -1e30f; lq[k] = -1e30f;
        }
        mlg = fmaxf(mlg, lg[k]);
        mlp = fmaxf(mlp, lq[k]);
    }
    #pragma unroll
    for (int o = 16; o; o >>= 1) {
        mlg = fmaxf(mlg, __shfl_xor_sync(0xffffffffu, mlg, o));
        mlp = fmaxf(mlp, __shfl_xor_sync(0xffffffffu, mlp, o));
    }
    float se = 0.f, sl = 0.f;
    #pragma unroll
    for (int k = 0; k < 4; ++k) {
        if (lane + 32 * k < CC) {
            se += __expf(lq[k] - mlp);
            sl += __expf(lg[k] - mlg);
        }
    }
    #pragma unroll
    for (int o = 16; o; o >>= 1) {
        se += __shfl_xor_sync(0xffffffffu, se, o);
        sl += __shfl_xor_sync(0xffffffffu, sl, o);
    }
    float marg = mlp + __logf(se);
    float logev = fminf(marg + 80.992775903f, 10.f);
    float E = __expf(logev) / sl;

    float* o = out + (size_t)n * (CC + 1);
    #pragma unroll
    for (int k = 0; k < 4; ++k) {
        int cc = lane + 32 * k;
        if (cc < CC)
            o[cc] = __logf(fmaf(E, __expf(lg[k] - mlg), 1.f));
    }
    if (lane == 0)
        o[CC] = g_lp[(size_t)labels[n] * NN + n];
}

extern "C" void kernel_launch(void* const* d_in, const int* in_sizes, int n_in,
                              void* d_out, int out_size) {
    const float* x      = (const float*)d_in[0];
    const int*   labels = (const int*)d_in[1];
    const float* freq   = (const float*)d_in[2];
    const float* z0     = (const float*)d_in[3];
    const float* ap     = (const float*)d_in[4];
    const float* bp     = (const float*)d_in[5];
    const float* W      = (const float*)d_in[6];
    const float* b      = (const float*)d_in[7];
    float* out = (float*)d_out;

    cudaFuncSetAttribute(flow_kernel, cudaFuncAttributeMaxDynamicSharedMemorySize, SMEM_BYTES);

    dim3 grid(NN / 128, HC);
    flow_kernel<<<grid, 128, SMEM_BYTES>>>(x, z0, ap, bp);
    out_kernel<<<NN / 8, 256>>>(x, labels, freq, W, b, out);
}